// round 1
// baseline (speedup 1.0000x reference)
#include <cuda_runtime.h>

#define DIMV   2048
#define SV     4
#define NTV    5          // S + V
#define NV     2048
#define BV     4
#define TPB    256
#define CHUNKS (DIMV / (4 * TPB))   // 2 float4 chunks per thread per row
#define EPSV   1e-5f

// Scratch for transposed, weight-folded gate matrices (no allocation allowed).
__device__ float g_gT[NTV * DIMV];   // gT[t][d] = norm_weight[d] * dynamic_alpha_fn[d][t]
__device__ float g_gb[DIMV];         // gb[d]    = norm_weight[d] * dynamic_beta_fn[d]

__global__ void prep_kernel(const float* __restrict__ w,
                            const float* __restrict__ afn,
                            const float* __restrict__ bfn) {
    int i = blockIdx.x * blockDim.x + threadIdx.x;
    if (i < DIMV) {
        float wv = w[i];
#pragma unroll
        for (int t = 0; t < NTV; t++)
            g_gT[t * DIMV + i] = wv * afn[i * NTV + t];
        g_gb[i] = wv * bfn[i];
    }
}

__device__ __forceinline__ float warp_sum(float v) {
#pragma unroll
    for (int o = 16; o > 0; o >>= 1)
        v += __shfl_xor_sync(0xffffffffu, v, o);
    return v;
}

__global__ __launch_bounds__(TPB) void hyper_kernel(
    const float* __restrict__ res,
    const float* __restrict__ static_beta,
    const float* __restrict__ static_alpha,
    const float* __restrict__ p_ascale,
    const float* __restrict__ p_bscale,
    float* __restrict__ out)
{
    __shared__ float sr[SV][DIMV];          // residual tile, 32 KB
    __shared__ float sred[TPB / 32][SV * 6];
    __shared__ float s_mu[SV], s_rsig[SV];
    __shared__ float s_alpha[SV][NTV];
    __shared__ float s_beta[SV];

    const int tid  = threadIdx.x;
    const int warp = tid >> 5;
    const int lane = tid & 31;

    const int token = blockIdx.x;           // 0 .. B*N-1
    const int b = token / NV;
    const int n = token - b * NV;
    const size_t rowstride = (size_t)NV * DIMV;   // stride between s-rows
    const float* base  = res + (size_t)(b * SV) * rowstride + (size_t)n * DIMV;
    float*       obase = out + (size_t)(b * SV) * rowstride + (size_t)n * DIMV;

    // ---- Pass A: load residual tile to SMEM, accumulate sum / sumsq ----
    float sum[SV], ssq[SV];
#pragma unroll
    for (int s = 0; s < SV; s++) { sum[s] = 0.f; ssq[s] = 0.f; }

#pragma unroll
    for (int s = 0; s < SV; s++) {
        const float4* rp = (const float4*)(base + (size_t)s * rowstride);
        float4* sp = (float4*)sr[s];
#pragma unroll
        for (int k = 0; k < CHUNKS; k++) {
            int idx = tid + k * TPB;
            float4 v = rp[idx];
            sp[idx] = v;
            sum[s] += v.x + v.y + v.z + v.w;
            ssq[s] += v.x * v.x + v.y * v.y + v.z * v.z + v.w * v.w;
        }
    }

#pragma unroll
    for (int s = 0; s < SV; s++) {
        sum[s] = warp_sum(sum[s]);
        ssq[s] = warp_sum(ssq[s]);
    }
    if (lane == 0) {
#pragma unroll
        for (int s = 0; s < SV; s++) {
            sred[warp][s]      = sum[s];
            sred[warp][SV + s] = ssq[s];
        }
    }
    __syncthreads();
    if (tid < SV) {
        float t1 = 0.f, t2 = 0.f;
#pragma unroll
        for (int w = 0; w < TPB / 32; w++) { t1 += sred[w][tid]; t2 += sred[w][SV + tid]; }
        float mu  = t1 * (1.f / DIMV);
        float var = t2 * (1.f / DIMV) - mu * mu;
        s_mu[tid]   = mu;
        s_rsig[tid] = rsqrtf(var + EPSV);
    }
    __syncthreads();

    float mu[SV];
#pragma unroll
    for (int s = 0; s < SV; s++) mu[s] = s_mu[s];

    // ---- Pass B: gate dot products: (r - mu) . (w*afn[:,t]) and (r - mu) . (w*bfn) ----
    float acc[SV][6];
#pragma unroll
    for (int s = 0; s < SV; s++)
#pragma unroll
        for (int u = 0; u < 6; u++) acc[s][u] = 0.f;

#pragma unroll
    for (int k = 0; k < CHUNKS; k++) {
        int idx = tid + k * TPB;
        float4 g[NTV];
#pragma unroll
        for (int t = 0; t < NTV; t++)
            g[t] = ((const float4*)g_gT)[t * (DIMV / 4) + idx];
        float4 gb = ((const float4*)g_gb)[idx];
#pragma unroll
        for (int s = 0; s < SV; s++) {
            float4 rv = ((const float4*)sr[s])[idx];
            float rx = rv.x - mu[s], ry = rv.y - mu[s];
            float rz = rv.z - mu[s], rw = rv.w - mu[s];
#pragma unroll
            for (int t = 0; t < NTV; t++)
                acc[s][t] += rx * g[t].x + ry * g[t].y + rz * g[t].z + rw * g[t].w;
            acc[s][5] += rx * gb.x + ry * gb.y + rz * gb.z + rw * gb.w;
        }
    }

#pragma unroll
    for (int s = 0; s < SV; s++)
#pragma unroll
        for (int u = 0; u < 6; u++) {
            float v = warp_sum(acc[s][u]);
            if (lane == 0) sred[warp][s * 6 + u] = v;
        }
    __syncthreads();
    if (tid < SV * 6) {
        float tot = 0.f;
#pragma unroll
        for (int w = 0; w < TPB / 32; w++) tot += sred[w][tid];
        int s = tid / 6, u = tid - s * 6;
        float dot = s_rsig[s] * tot;
        float th  = tanhf(dot);
        if (u < NTV) s_alpha[s][u] = th * p_ascale[0] + static_alpha[s * NTV + u];
        else         s_beta[s]     = th * p_bscale[0] + static_beta[s];
    }
    __syncthreads();

    // ---- Pass C: mix and write output ----
    float al[SV][NTV], be[SV];
#pragma unroll
    for (int s = 0; s < SV; s++) {
        be[s] = s_beta[s];
#pragma unroll
        for (int t = 0; t < NTV; t++) al[s][t] = s_alpha[s][t];
    }

#pragma unroll
    for (int k = 0; k < CHUNKS; k++) {
        int idx = tid + k * TPB;
        float4 rv[SV];
#pragma unroll
        for (int s = 0; s < SV; s++) rv[s] = ((const float4*)sr[s])[idx];

        float4 mix[NTV];
#pragma unroll
        for (int t = 0; t < NTV; t++) {
            mix[t].x = al[0][t] * rv[0].x;
            mix[t].y = al[0][t] * rv[0].y;
            mix[t].z = al[0][t] * rv[0].z;
            mix[t].w = al[0][t] * rv[0].w;
#pragma unroll
            for (int s = 1; s < SV; s++) {
                mix[t].x += al[s][t] * rv[s].x;
                mix[t].y += al[s][t] * rv[s].y;
                mix[t].z += al[s][t] * rv[s].z;
                mix[t].w += al[s][t] * rv[s].w;
            }
        }
#pragma unroll
        for (int s = 0; s < SV; s++) {
            float4 o;
            o.x = mix[0].x * be[s] + mix[s + 1].x;
            o.y = mix[0].y * be[s] + mix[s + 1].y;
            o.z = mix[0].z * be[s] + mix[s + 1].z;
            o.w = mix[0].w * be[s] + mix[s + 1].w;
            ((float4*)(obase + (size_t)s * rowstride))[idx] = o;
        }
    }
}

extern "C" void kernel_launch(void* const* d_in, const int* in_sizes, int n_in,
                              void* d_out, int out_size) {
    const float* res    = (const float*)d_in[0];
    const float* w      = (const float*)d_in[1];
    const float* sbeta  = (const float*)d_in[2];
    const float* salpha = (const float*)d_in[3];
    const float* afn    = (const float*)d_in[4];
    const float* ascale = (const float*)d_in[5];
    const float* bfn    = (const float*)d_in[6];
    const float* bscale = (const float*)d_in[7];
    float* out = (float*)d_out;

    prep_kernel<<<(DIMV + 255) / 256, 256>>>(w, afn, bfn);
    hyper_kernel<<<BV * NV, TPB>>>(res, sbeta, salpha, ascale, bscale, out);
}

// round 2
// speedup vs baseline: 1.0106x; 1.0106x over previous
#include <cuda_runtime.h>

#define DIMV   2048
#define SV     4
#define NTV    5          // S + V
#define NV     2048
#define BV     4
#define TPB    256
#define CHUNKS (DIMV / (4 * TPB))   // 2 float4 chunks per thread per row
#define EPSV   1e-5f

// Scratch (no allocation allowed): transposed weight-folded gate matrices + column sums.
__device__ float g_gT[6 * DIMV];   // gT[t][d] = w[d]*afn[d][t] (t<5), gT[5][d] = w[d]*bfn[d]
__device__ float g_gsum[6];        // gsum[t]  = sum_d gT[t][d]

__global__ void prep_kernel(const float* __restrict__ w,
                            const float* __restrict__ afn,
                            const float* __restrict__ bfn) {
    __shared__ float sred[32][6];
    int tid = threadIdx.x;          // 1024 threads, 1 block
    float part[6] = {0.f, 0.f, 0.f, 0.f, 0.f, 0.f};
#pragma unroll
    for (int r = 0; r < 2; r++) {
        int i = tid + r * 1024;
        float wv = w[i];
#pragma unroll
        for (int t = 0; t < NTV; t++) {
            float v = wv * afn[i * NTV + t];
            g_gT[t * DIMV + i] = v;
            part[t] += v;
        }
        float vb = wv * bfn[i];
        g_gT[5 * DIMV + i] = vb;
        part[5] += vb;
    }
#pragma unroll
    for (int u = 0; u < 6; u++)
#pragma unroll
        for (int o = 16; o > 0; o >>= 1)
            part[u] += __shfl_xor_sync(0xffffffffu, part[u], o);
    if ((tid & 31) == 0)
#pragma unroll
        for (int u = 0; u < 6; u++) sred[tid >> 5][u] = part[u];
    __syncthreads();
    if (tid < 6) {
        float tot = 0.f;
#pragma unroll
        for (int wp = 0; wp < 32; wp++) tot += sred[wp][tid];
        g_gsum[tid] = tot;
    }
}

__device__ __forceinline__ float warp_sum(float v) {
#pragma unroll
    for (int o = 16; o > 0; o >>= 1)
        v += __shfl_xor_sync(0xffffffffu, v, o);
    return v;
}

__global__ __launch_bounds__(TPB, 2) void hyper_kernel(
    const float* __restrict__ res,
    const float* __restrict__ static_beta,
    const float* __restrict__ static_alpha,
    const float* __restrict__ p_ascale,
    const float* __restrict__ p_bscale,
    float* __restrict__ out)
{
    __shared__ float sred[TPB / 32][SV * 8];   // per-warp: 4 streams x (sum, ssq, 6 dots)
    __shared__ float s_alpha[SV][NTV];
    __shared__ float s_beta[SV];

    const int tid  = threadIdx.x;
    const int warp = tid >> 5;
    const int lane = tid & 31;

    const int token = blockIdx.x;              // 0 .. B*N-1
    const int b = token >> 11;                 // / NV
    const int n = token & (NV - 1);
    const size_t rowstride = (size_t)NV * DIMV;
    const float* base  = res + (size_t)(b * SV) * rowstride + (size_t)n * DIMV;
    float*       obase = out + (size_t)(b * SV) * rowstride + (size_t)n * DIMV;

    // ---- Single fused pass: load residuals to REGISTERS, accumulate
    //      sum, sumsq, and 6 raw gate dots (un-centered) per stream. ----
    float4 rv[SV][CHUNKS];
    float acc[SV][8];                          // [0]=sum [1]=ssq [2..7]=dots
#pragma unroll
    for (int s = 0; s < SV; s++)
#pragma unroll
        for (int u = 0; u < 8; u++) acc[s][u] = 0.f;

#pragma unroll
    for (int k = 0; k < CHUNKS; k++) {
        const int idx = tid + k * TPB;
        float4 g[6];
#pragma unroll
        for (int t = 0; t < 6; t++)
            g[t] = ((const float4*)g_gT)[t * (DIMV / 4) + idx];
#pragma unroll
        for (int s = 0; s < SV; s++) {
            float4 v = ((const float4*)(base + (size_t)s * rowstride))[idx];
            rv[s][k] = v;
            acc[s][0] += v.x + v.y + v.z + v.w;
            acc[s][1] += v.x * v.x + v.y * v.y + v.z * v.z + v.w * v.w;
#pragma unroll
            for (int t = 0; t < 6; t++)
                acc[s][2 + t] += v.x * g[t].x + v.y * g[t].y + v.z * g[t].z + v.w * g[t].w;
        }
    }

    // ---- One reduction round: 32 values ----
#pragma unroll
    for (int s = 0; s < SV; s++)
#pragma unroll
        for (int u = 0; u < 8; u++) {
            float v = warp_sum(acc[s][u]);
            if (lane == 0) sred[warp][s * 8 + u] = v;
        }
    __syncthreads();

    // 24 threads finalize: (s, j) j=0..5 -> 5 alphas + 1 beta per stream
    if (tid < SV * 6) {
        const int s = tid / 6, j = tid - s * 6;
        float tsum = 0.f, tssq = 0.f, tdot = 0.f;
#pragma unroll
        for (int w = 0; w < TPB / 32; w++) {
            tsum += sred[w][s * 8 + 0];
            tssq += sred[w][s * 8 + 1];
            tdot += sred[w][s * 8 + 2 + j];
        }
        const float mu   = tsum * (1.f / DIMV);
        const float var  = tssq * (1.f / DIMV) - mu * mu;
        const float rsig = rsqrtf(var + EPSV);
        const float dotc = (tdot - mu * g_gsum[j]) * rsig;
        const float th   = tanhf(dotc);
        if (j < NTV) s_alpha[s][j] = th * p_ascale[0] + static_alpha[s * NTV + j];
        else         s_beta[s]     = th * p_bscale[0] + static_beta[s];
    }
    __syncthreads();

    // ---- Mix from registers and write output ----
    float al[SV][NTV], be[SV];
#pragma unroll
    for (int s = 0; s < SV; s++) {
        be[s] = s_beta[s];
#pragma unroll
        for (int t = 0; t < NTV; t++) al[s][t] = s_alpha[s][t];
    }

#pragma unroll
    for (int k = 0; k < CHUNKS; k++) {
        const int idx = tid + k * TPB;
        float4 mix[NTV];
#pragma unroll
        for (int t = 0; t < NTV; t++) {
            mix[t].x = al[0][t] * rv[0][k].x;
            mix[t].y = al[0][t] * rv[0][k].y;
            mix[t].z = al[0][t] * rv[0][k].z;
            mix[t].w = al[0][t] * rv[0][k].w;
#pragma unroll
            for (int s = 1; s < SV; s++) {
                mix[t].x += al[s][t] * rv[s][k].x;
                mix[t].y += al[s][t] * rv[s][k].y;
                mix[t].z += al[s][t] * rv[s][k].z;
                mix[t].w += al[s][t] * rv[s][k].w;
            }
        }
#pragma unroll
        for (int s = 0; s < SV; s++) {
            float4 o;
            o.x = mix[0].x * be[s] + mix[s + 1].x;
            o.y = mix[0].y * be[s] + mix[s + 1].y;
            o.z = mix[0].z * be[s] + mix[s + 1].z;
            o.w = mix[0].w * be[s] + mix[s + 1].w;
            ((float4*)(obase + (size_t)s * rowstride))[idx] = o;
        }
    }
}

extern "C" void kernel_launch(void* const* d_in, const int* in_sizes, int n_in,
                              void* d_out, int out_size) {
    const float* res    = (const float*)d_in[0];
    const float* w      = (const float*)d_in[1];
    const float* sbeta  = (const float*)d_in[2];
    const float* salpha = (const float*)d_in[3];
    const float* afn    = (const float*)d_in[4];
    const float* ascale = (const float*)d_in[5];
    const float* bfn    = (const float*)d_in[6];
    const float* bscale = (const float*)d_in[7];
    float* out = (float*)d_out;

    prep_kernel<<<1, 1024>>>(w, afn, bfn);
    hyper_kernel<<<BV * NV, TPB>>>(res, sbeta, salpha, ascale, bscale, out);
}

// round 3
// speedup vs baseline: 1.0314x; 1.0205x over previous
#include <cuda_runtime.h>

#define DIMV   2048
#define SV     4
#define NTV    5          // S + V
#define NV     2048
#define BV     4
#define TPB    256
#define CHUNKS (DIMV / (4 * TPB))   // 2 float4 chunks per thread per row
#define EPSV   1e-5f

// Scratch (no allocation allowed): transposed weight-folded gate matrices + column sums.
__device__ float g_gT[6 * DIMV];   // gT[t][d] = w[d]*afn[d][t] (t<5), gT[5][d] = w[d]*bfn[d]
__device__ float g_gsum[6];        // gsum[t]  = sum_d gT[t][d]

__global__ void prep_kernel(const float* __restrict__ w,
                            const float* __restrict__ afn,
                            const float* __restrict__ bfn) {
    __shared__ float sred[32][6];
    int tid = threadIdx.x;          // 1024 threads, 1 block
    float part[6] = {0.f, 0.f, 0.f, 0.f, 0.f, 0.f};
#pragma unroll
    for (int r = 0; r < 2; r++) {
        int i = tid + r * 1024;
        float wv = w[i];
#pragma unroll
        for (int t = 0; t < NTV; t++) {
            float v = wv * afn[i * NTV + t];
            g_gT[t * DIMV + i] = v;
            part[t] += v;
        }
        float vb = wv * bfn[i];
        g_gT[5 * DIMV + i] = vb;
        part[5] += vb;
    }
#pragma unroll
    for (int u = 0; u < 6; u++)
#pragma unroll
        for (int o = 16; o > 0; o >>= 1)
            part[u] += __shfl_xor_sync(0xffffffffu, part[u], o);
    if ((tid & 31) == 0)
#pragma unroll
        for (int u = 0; u < 6; u++) sred[tid >> 5][u] = part[u];
    __syncthreads();
    if (tid < 6) {
        float tot = 0.f;
#pragma unroll
        for (int wp = 0; wp < 32; wp++) tot += sred[wp][tid];
        g_gsum[tid] = tot;
    }
}

__device__ __forceinline__ float warp_sum(float v) {
#pragma unroll
    for (int o = 16; o > 0; o >>= 1)
        v += __shfl_xor_sync(0xffffffffu, v, o);
    return v;
}

__global__ __launch_bounds__(TPB, 3) void hyper_kernel(
    const float* __restrict__ res,
    const float* __restrict__ static_beta,
    const float* __restrict__ static_alpha,
    const float* __restrict__ p_ascale,
    const float* __restrict__ p_bscale,
    float* __restrict__ out)
{
    __shared__ float sred[TPB / 32][SV * 8];   // per-warp: 4 streams x (sum, ssq, 6 dots)
    __shared__ float s_alpha[SV][NTV];
    __shared__ float s_beta[SV];
    __shared__ float s_C[SV][SV];              // out[s] = sum_sp C[s][sp] * r[sp]

    const int tid  = threadIdx.x;
    const int warp = tid >> 5;
    const int lane = tid & 31;

    const int token = blockIdx.x;              // 0 .. B*N-1
    const int b = token >> 11;                 // / NV
    const int n = token & (NV - 1);
    const size_t rowstride = (size_t)NV * DIMV;
    const float* base  = res + (size_t)(b * SV) * rowstride + (size_t)n * DIMV;
    float*       obase = out + (size_t)(b * SV) * rowstride + (size_t)n * DIMV;

    // ---- Fused pass A: stream residuals once, accumulate per-stream
    //      sum, sumsq, and 6 raw (un-centered) gate dots. Residuals are
    //      NOT retained in registers — pass C re-reads them from L1. ----
    float acc[SV][8];                          // [0]=sum [1]=ssq [2..7]=dots
#pragma unroll
    for (int s = 0; s < SV; s++)
#pragma unroll
        for (int u = 0; u < 8; u++) acc[s][u] = 0.f;

#pragma unroll
    for (int k = 0; k < CHUNKS; k++) {
        const int idx = tid + k * TPB;
        // Issue the 4 long-latency residual loads first (independent).
        float4 v[SV];
#pragma unroll
        for (int s = 0; s < SV; s++)
            v[s] = __ldg(&((const float4*)(base + (size_t)s * rowstride))[idx]);
        // Gate loads (L1/L2-resident after the first wave).
        float4 g[6];
#pragma unroll
        for (int t = 0; t < 6; t++)
            g[t] = ((const float4*)g_gT)[t * (DIMV / 4) + idx];
#pragma unroll
        for (int s = 0; s < SV; s++) {
            acc[s][0] += v[s].x + v[s].y + v[s].z + v[s].w;
            acc[s][1] += v[s].x * v[s].x + v[s].y * v[s].y + v[s].z * v[s].z + v[s].w * v[s].w;
#pragma unroll
            for (int t = 0; t < 6; t++)
                acc[s][2 + t] += v[s].x * g[t].x + v[s].y * g[t].y
                               + v[s].z * g[t].z + v[s].w * g[t].w;
        }
    }

    // ---- One reduction round: 32 values ----
#pragma unroll
    for (int s = 0; s < SV; s++)
#pragma unroll
        for (int u = 0; u < 8; u++) {
            float v = warp_sum(acc[s][u]);
            if (lane == 0) sred[warp][s * 8 + u] = v;
        }
    __syncthreads();

    // 24 threads finalize alpha/beta
    if (tid < SV * 6) {
        const int s = tid / 6, j = tid - s * 6;
        float tsum = 0.f, tssq = 0.f, tdot = 0.f;
#pragma unroll
        for (int w = 0; w < TPB / 32; w++) {
            tsum += sred[w][s * 8 + 0];
            tssq += sred[w][s * 8 + 1];
            tdot += sred[w][s * 8 + 2 + j];
        }
        const float mu   = tsum * (1.f / DIMV);
        const float var  = tssq * (1.f / DIMV) - mu * mu;
        const float rsig = rsqrtf(var + EPSV);
        const float dotc = (tdot - mu * g_gsum[j]) * rsig;
        const float th   = tanhf(dotc);
        if (j < NTV) s_alpha[s][j] = th * p_ascale[0] + static_alpha[s * NTV + j];
        else         s_beta[s]     = th * p_bscale[0] + static_beta[s];
    }
    __syncthreads();

    // 16 threads fold alpha/beta into the 4x4 mixing matrix
    if (tid < SV * SV) {
        const int s = tid >> 2, sp = tid & 3;
        s_C[s][sp] = s_beta[s] * s_alpha[sp][0] + s_alpha[sp][s + 1];
    }
    __syncthreads();

    float Cm[SV][SV];
#pragma unroll
    for (int s = 0; s < SV; s++)
#pragma unroll
        for (int sp = 0; sp < SV; sp++) Cm[s][sp] = s_C[s][sp];

    // ---- Pass C: re-read residuals (L1 hits), apply 4x4 mix, write ----
#pragma unroll
    for (int k = 0; k < CHUNKS; k++) {
        const int idx = tid + k * TPB;
        float4 v[SV];
#pragma unroll
        for (int s = 0; s < SV; s++)
            v[s] = __ldg(&((const float4*)(base + (size_t)s * rowstride))[idx]);
#pragma unroll
        for (int s = 0; s < SV; s++) {
            float4 o;
            o.x = Cm[s][0] * v[0].x; o.y = Cm[s][0] * v[0].y;
            o.z = Cm[s][0] * v[0].z; o.w = Cm[s][0] * v[0].w;
#pragma unroll
            for (int sp = 1; sp < SV; sp++) {
                o.x += Cm[s][sp] * v[sp].x;
                o.y += Cm[s][sp] * v[sp].y;
                o.z += Cm[s][sp] * v[sp].z;
                o.w += Cm[s][sp] * v[sp].w;
            }
            ((float4*)(obase + (size_t)s * rowstride))[idx] = o;
        }
    }
}

extern "C" void kernel_launch(void* const* d_in, const int* in_sizes, int n_in,
                              void* d_out, int out_size) {
    const float* res    = (const float*)d_in[0];
    const float* w      = (const float*)d_in[1];
    const float* sbeta  = (const float*)d_in[2];
    const float* salpha = (const float*)d_in[3];
    const float* afn    = (const float*)d_in[4];
    const float* ascale = (const float*)d_in[5];
    const float* bfn    = (const float*)d_in[6];
    const float* bscale = (const float*)d_in[7];
    float* out = (float*)d_out;

    prep_kernel<<<1, 1024>>>(w, afn, bfn);
    hyper_kernel<<<BV * NV, TPB>>>(res, sbeta, salpha, ascale, bscale, out);
}

// round 4
// speedup vs baseline: 1.2082x; 1.1714x over previous
#include <cuda_runtime.h>
#include <cuda_bf16.h>

#define DIMV   2048
#define SV     4
#define NTV    5          // S + V
#define NV     2048
#define BV     4
#define TPB    128
#define CHUNKS (DIMV / (4 * TPB))   // 4 float4 chunks per thread per row
#define QUADS  (DIMV / 4)           // 512 float4 groups per row
#define EPSV   1e-5f

// Scratch (no device allocation allowed).
// g_gp[j][q]: uint4 holding gates t=2j and t=2j+1 for dim group q, bf16-packed:
//   .x = bf16x2(g[2j][0],   g[2j][1])   .y = bf16x2(g[2j][2],   g[2j][3])
//   .z = bf16x2(g[2j+1][0], g[2j+1][1]) .w = bf16x2(g[2j+1][2], g[2j+1][3])
// where g[t][i] = norm_weight * (afn[:,t] for t<5, bfn for t=5), rounded to bf16.
__device__ uint4 g_gp[3][QUADS];
__device__ float g_gsum[6];        // column sums of the ROUNDED gate values

__global__ void prep_kernel(const float* __restrict__ w,
                            const float* __restrict__ afn,
                            const float* __restrict__ bfn) {
    __shared__ float sred[16][6];
    const int tid = threadIdx.x;          // 512 threads, 1 block; one per dim-quad
    const int d0  = tid * 4;

    float gv[6][4];
#pragma unroll
    for (int i = 0; i < 4; i++) {
        float wv = w[d0 + i];
#pragma unroll
        for (int t = 0; t < NTV; t++)
            gv[t][i] = wv * afn[(d0 + i) * NTV + t];
        gv[5][i] = wv * bfn[d0 + i];
    }

    float part[6];
#pragma unroll
    for (int j = 0; j < 3; j++) {
        const int t0 = 2 * j, t1 = 2 * j + 1;
        __nv_bfloat162 hx = __floats2bfloat162_rn(gv[t0][0], gv[t0][1]);
        __nv_bfloat162 hy = __floats2bfloat162_rn(gv[t0][2], gv[t0][3]);
        __nv_bfloat162 hz = __floats2bfloat162_rn(gv[t1][0], gv[t1][1]);
        __nv_bfloat162 hw = __floats2bfloat162_rn(gv[t1][2], gv[t1][3]);
        uint4 u;
        u.x = *reinterpret_cast<unsigned*>(&hx);
        u.y = *reinterpret_cast<unsigned*>(&hy);
        u.z = *reinterpret_cast<unsigned*>(&hz);
        u.w = *reinterpret_cast<unsigned*>(&hw);
        g_gp[j][tid] = u;
        // sums of the rounded values (so centering is exact w.r.t. what we use)
        float2 fx = __bfloat1622float2(hx), fy = __bfloat1622float2(hy);
        float2 fz = __bfloat1622float2(hz), fw = __bfloat1622float2(hw);
        part[t0] = fx.x + fx.y + fy.x + fy.y;
        part[t1] = fz.x + fz.y + fw.x + fw.y;
    }

#pragma unroll
    for (int u = 0; u < 6; u++)
#pragma unroll
        for (int o = 16; o > 0; o >>= 1)
            part[u] += __shfl_xor_sync(0xffffffffu, part[u], o);
    if ((tid & 31) == 0)
#pragma unroll
        for (int u = 0; u < 6; u++) sred[tid >> 5][u] = part[u];
    __syncthreads();
    if (tid < 6) {
        float tot = 0.f;
#pragma unroll
        for (int wp = 0; wp < 16; wp++) tot += sred[wp][tid];
        g_gsum[tid] = tot;
    }
}

__device__ __forceinline__ float warp_sum(float v) {
#pragma unroll
    for (int o = 16; o > 0; o >>= 1)
        v += __shfl_xor_sync(0xffffffffu, v, o);
    return v;
}

__global__ __launch_bounds__(TPB, 6) void hyper_kernel(
    const float* __restrict__ res,
    const float* __restrict__ static_beta,
    const float* __restrict__ static_alpha,
    const float* __restrict__ p_ascale,
    const float* __restrict__ p_bscale,
    float* __restrict__ out)
{
    __shared__ float sred[TPB / 32][SV * 8];
    __shared__ float s_alpha[SV][NTV];
    __shared__ float s_beta[SV];
    __shared__ float s_C[SV][SV];

    const int tid  = threadIdx.x;
    const int warp = tid >> 5;
    const int lane = tid & 31;

    const int token = blockIdx.x;              // 0 .. B*N-1
    const int b = token >> 11;
    const int n = token & (NV - 1);
    const size_t rowstride = (size_t)NV * DIMV;
    const float* base  = res + (size_t)(b * SV) * rowstride + (size_t)n * DIMV;
    float*       obase = out + (size_t)(b * SV) * rowstride + (size_t)n * DIMV;

    // ---- Fused pass A: stream residuals, accumulate sum/ssq + 6 raw gate dots ----
    float acc[SV][8];                          // [0]=sum [1]=ssq [2..7]=dots t0..t5
#pragma unroll
    for (int s = 0; s < SV; s++)
#pragma unroll
        for (int u = 0; u < 8; u++) acc[s][u] = 0.f;

#pragma unroll
    for (int k = 0; k < CHUNKS; k++) {
        const int idx = tid + k * TPB;
        float4 v[SV];
#pragma unroll
        for (int s = 0; s < SV; s++)
            v[s] = __ldg(&((const float4*)(base + (size_t)s * rowstride))[idx]);

#pragma unroll
        for (int s = 0; s < SV; s++) {
            acc[s][0] += v[s].x + v[s].y + v[s].z + v[s].w;
            acc[s][1] += v[s].x * v[s].x + v[s].y * v[s].y
                       + v[s].z * v[s].z + v[s].w * v[s].w;
        }

#pragma unroll
        for (int j = 0; j < 3; j++) {
            uint4 p = g_gp[j][idx];
            float2 fx = __bfloat1622float2(*reinterpret_cast<__nv_bfloat162*>(&p.x));
            float2 fy = __bfloat1622float2(*reinterpret_cast<__nv_bfloat162*>(&p.y));
            float2 fz = __bfloat1622float2(*reinterpret_cast<__nv_bfloat162*>(&p.z));
            float2 fw = __bfloat1622float2(*reinterpret_cast<__nv_bfloat162*>(&p.w));
#pragma unroll
            for (int s = 0; s < SV; s++) {
                acc[s][2 + 2 * j]     += v[s].x * fx.x + v[s].y * fx.y
                                       + v[s].z * fy.x + v[s].w * fy.y;
                acc[s][2 + 2 * j + 1] += v[s].x * fz.x + v[s].y * fz.y
                                       + v[s].z * fw.x + v[s].w * fw.y;
            }
        }
    }

    // ---- One reduction round: 32 values per warp ----
#pragma unroll
    for (int s = 0; s < SV; s++)
#pragma unroll
        for (int u = 0; u < 8; u++) {
            float v = warp_sum(acc[s][u]);
            if (lane == 0) sred[warp][s * 8 + u] = v;
        }
    __syncthreads();

    // 24 threads finalize alpha/beta
    if (tid < SV * 6) {
        const int s = tid / 6, j = tid - s * 6;
        float tsum = 0.f, tssq = 0.f, tdot = 0.f;
#pragma unroll
        for (int w = 0; w < TPB / 32; w++) {
            tsum += sred[w][s * 8 + 0];
            tssq += sred[w][s * 8 + 1];
            tdot += sred[w][s * 8 + 2 + j];
        }
        const float mu   = tsum * (1.f / DIMV);
        const float var  = tssq * (1.f / DIMV) - mu * mu;
        const float rsig = rsqrtf(var + EPSV);
        const float dotc = (tdot - mu * g_gsum[j]) * rsig;
        const float th   = tanhf(dotc);
        if (j < NTV) s_alpha[s][j] = th * p_ascale[0] + static_alpha[s * NTV + j];
        else         s_beta[s]     = th * p_bscale[0] + static_beta[s];
    }
    __syncthreads();

    if (tid < SV * SV) {
        const int s = tid >> 2, sp = tid & 3;
        s_C[s][sp] = s_beta[s] * s_alpha[sp][0] + s_alpha[sp][s + 1];
    }
    __syncthreads();

    float Cm[SV][SV];
#pragma unroll
    for (int s = 0; s < SV; s++)
#pragma unroll
        for (int sp = 0; sp < SV; sp++) Cm[s][sp] = s_C[s][sp];

    // ---- Pass C: re-read residuals (L1 hits), 4x4 mix, streaming stores ----
#pragma unroll
    for (int k = 0; k < CHUNKS; k++) {
        const int idx = tid + k * TPB;
        float4 v[SV];
#pragma unroll
        for (int s = 0; s < SV; s++)
            v[s] = __ldg(&((const float4*)(base + (size_t)s * rowstride))[idx]);
#pragma unroll
        for (int s = 0; s < SV; s++) {
            float4 o;
            o.x = Cm[s][0] * v[0].x; o.y = Cm[s][0] * v[0].y;
            o.z = Cm[s][0] * v[0].z; o.w = Cm[s][0] * v[0].w;
#pragma unroll
            for (int sp = 1; sp < SV; sp++) {
                o.x += Cm[s][sp] * v[sp].x;
                o.y += Cm[s][sp] * v[sp].y;
                o.z += Cm[s][sp] * v[sp].z;
                o.w += Cm[s][sp] * v[sp].w;
            }
            __stcs(&((float4*)(obase + (size_t)s * rowstride))[idx], o);
        }
    }
}

extern "C" void kernel_launch(void* const* d_in, const int* in_sizes, int n_in,
                              void* d_out, int out_size) {
    const float* res    = (const float*)d_in[0];
    const float* w      = (const float*)d_in[1];
    const float* sbeta  = (const float*)d_in[2];
    const float* salpha = (const float*)d_in[3];
    const float* afn    = (const float*)d_in[4];
    const float* ascale = (const float*)d_in[5];
    const float* bfn    = (const float*)d_in[6];
    const float* bscale = (const float*)d_in[7];
    float* out = (float*)d_out;

    prep_kernel<<<1, 512>>>(w, afn, bfn);
    hyper_kernel<<<BV * NV, TPB>>>(res, sbeta, salpha, ascale, bscale, out);
}